// round 1
// baseline (speedup 1.0000x reference)
#include <cuda_runtime.h>

// Complex-valued attention, fp32 SIMT flash-attention baseline.
// out = ((softmax(|QK^T/t|) * phase(QK^T)) @ V), stacked [re, im].

#define S_LEN    2048
#define DHEAD    64
#define QPB      8      // queries per CTA (one warp each)
#define KT       32     // key-tile (one lane per key)
#define NTHREADS 256

__global__ __launch_bounds__(NTHREADS, 2)
void cv_attn_kernel(
    const float* __restrict__ qr, const float* __restrict__ qi,
    const float* __restrict__ kr, const float* __restrict__ ki,
    const float* __restrict__ vr, const float* __restrict__ vi,
    float* __restrict__ out, long long plane)
{
    // K transposed [d][key] with +1 float2 pad: STS (d varies in warp) banks 2d%32,
    // LDS (lane=key varies) banks (2d+2l)%32 — both conflict-free per 16-lane phase.
    __shared__ float2 qs[QPB][DHEAD];
    __shared__ float2 ks[DHEAD][KT + 1];
    __shared__ float2 vs[KT][DHEAD];

    const int tid  = threadIdx.x;
    const int w    = tid >> 5;      // warp = query within CTA
    const int lane = tid & 31;
    const int bh   = blockIdx.y;
    const int s0   = blockIdx.x * QPB;

    const long long bh_base = (long long)bh * S_LEN * DHEAD;

    // Load this CTA's 8 queries into shared (re,im interleaved).
    for (int idx = tid; idx < QPB * DHEAD; idx += NTHREADS) {
        int qq = idx >> 6, d = idx & 63;
        long long g = bh_base + (long long)(s0 + qq) * DHEAD + d;
        qs[qq][d] = make_float2(qr[g], qi[g]);
    }

    float M = -1e30f, L = 0.f;
    float aR0 = 0.f, aR1 = 0.f, aI0 = 0.f, aI1 = 0.f;  // acc[d=lane], acc[d=lane+32]
    const float inv_t = 0.125f;  // 1/TEMPERATURE

    for (int t0 = 0; t0 < S_LEN; t0 += KT) {
        __syncthreads();   // previous tile's compute done (and q stores on iter 0)
        // Cooperative K/V tile load: consecutive tid -> consecutive d (coalesced 128B).
        for (int idx = tid; idx < KT * DHEAD; idx += NTHREADS) {
            int ky = idx >> 6, d = idx & 63;
            long long g = bh_base + (long long)(t0 + ky) * DHEAD + d;
            ks[d][ky] = make_float2(kr[g], ki[g]);
            vs[ky][d] = make_float2(vr[g], vi[g]);
        }
        __syncthreads();

        // --- QK^T: lane's key vs warp's query, full D=64 dot (complex, no conj) ---
        float re = 0.f, im = 0.f;
        #pragma unroll
        for (int d = 0; d < DHEAD; d++) {
            float2 kk = ks[d][lane];
            float2 qq = qs[w][d];        // broadcast LDS
            re = fmaf(qq.x, kk.x, re);
            re = fmaf(-qq.y, kk.y, re);
            im = fmaf(qq.x, kk.y, im);
            im = fmaf(qq.y, kk.x, im);
        }
        re *= inv_t; im *= inv_t;

        // --- online softmax over magnitudes ---
        float mag = sqrtf(fmaf(re, re, im * im));
        float m = mag;
        #pragma unroll
        for (int off = 16; off > 0; off >>= 1)
            m = fmaxf(m, __shfl_xor_sync(0xffffffffu, m, off));
        float newM = fmaxf(M, m);
        float corr = __expf(M - newM);          // 0 on first tile (M = -1e30)
        float e    = __expf(mag - newM);
        float p    = e / fmaxf(mag, 1e-12f);    // exp-weight / |z| (phase guard)
        float wr = re * p, wi = im * p;         // complex weight for this key
        float ls = e;
        #pragma unroll
        for (int off = 16; off > 0; off >>= 1)
            ls += __shfl_xor_sync(0xffffffffu, ls, off);
        L = fmaf(L, corr, ls);
        aR0 *= corr; aR1 *= corr; aI0 *= corr; aI1 *= corr;

        // --- A @ V: broadcast lane ky's weight, all lanes cover d and d+32 ---
        #pragma unroll
        for (int ky = 0; ky < KT; ky++) {
            float ar = __shfl_sync(0xffffffffu, wr, ky);
            float ai = __shfl_sync(0xffffffffu, wi, ky);
            float2 v0 = vs[ky][lane];
            float2 v1 = vs[ky][lane + 32];
            aR0 = fmaf(ar, v0.x, aR0); aR0 = fmaf(-ai, v0.y, aR0);
            aI0 = fmaf(ar, v0.y, aI0); aI0 = fmaf(ai, v0.x, aI0);
            aR1 = fmaf(ar, v1.x, aR1); aR1 = fmaf(-ai, v1.y, aR1);
            aI1 = fmaf(ar, v1.y, aI1); aI1 = fmaf(ai, v1.x, aI1);
        }
        M = newM;
    }

    float invL = 1.0f / L;
    long long ob = bh_base + (long long)(s0 + w) * DHEAD;
    out[ob + lane]                = aR0 * invL;
    out[ob + lane + 32]           = aR1 * invL;
    out[plane + ob + lane]        = aI0 * invL;
    out[plane + ob + lane + 32]   = aI1 * invL;
}

extern "C" void kernel_launch(void* const* d_in, const int* in_sizes, int n_in,
                              void* d_out, int out_size) {
    const float* qr = (const float*)d_in[0];
    const float* qi = (const float*)d_in[1];
    const float* kr = (const float*)d_in[2];
    const float* ki = (const float*)d_in[3];
    const float* vr = (const float*)d_in[4];
    const float* vi = (const float*)d_in[5];

    const long long plane = (long long)in_sizes[0];         // B*H*S*D
    const int bh = (int)(plane / ((long long)S_LEN * DHEAD)); // 32

    dim3 grid(S_LEN / QPB, bh);   // x fastest -> CTAs of one head co-resident (L2 reuse)
    cv_attn_kernel<<<grid, NTHREADS>>>(qr, qi, kr, ki, vr, vi, (float*)d_out, plane);
}

// round 2
// speedup vs baseline: 1.4684x; 1.4684x over previous
#include <cuda_runtime.h>

// Complex-valued attention — register-tiled (4 queries/warp) + packed f32x2 FMA.
// out = (softmax(|QK^T/t|) * phase(QK^T)) @ V, stacked [re, im].

#define S_LEN    2048
#define DHEAD    64
#define G        4              // queries per warp
#define WARPS    8
#define NTHREADS 256
#define QPB      (G * WARPS)    // 32 queries per CTA
#define KT       32             // key tile (lane = key)

typedef unsigned long long u64;

__device__ __forceinline__ u64 pk2(float lo, float hi) {
    u64 r; asm("mov.b64 %0, {%1, %2};" : "=l"(r) : "f"(lo), "f"(hi)); return r;
}
__device__ __forceinline__ void upk2(u64 v, float& lo, float& hi) {
    asm("mov.b64 {%0, %1}, %2;" : "=f"(lo), "=f"(hi) : "l"(v));
}
__device__ __forceinline__ u64 fma2(u64 a, u64 b, u64 c) {
    u64 d; asm("fma.rn.f32x2 %0, %1, %2, %3;" : "=l"(d) : "l"(a), "l"(b), "l"(c)); return d;
}
__device__ __forceinline__ u64 mul2(u64 a, u64 b) {
    u64 d; asm("mul.rn.f32x2 %0, %1, %2;" : "=l"(d) : "l"(a), "l"(b)); return d;
}

// dynamic smem layout (bytes)
#define QS_OFF  0                                   // float4 [DHEAD][QPB+1]  {qr,qr,-qi,qi}/t
#define QS_SZ   (DHEAD * (QPB + 1) * 16)            // 33792
#define KS_OFF  (QS_OFF + QS_SZ)                    // float2 [DHEAD][KT+1]   {kr,ki}
#define KS_SZ   (DHEAD * (KT + 1) * 8)              // 16896
#define VS_OFF  (KS_OFF + KS_SZ)                    // float2 [KT][DHEAD]     {vr,vi}
#define VS_SZ   (KT * DHEAD * 8)                    // 16384
#define WS_OFF  (VS_OFF + VS_SZ)                    // float4 [WARPS][KT][G+1] {wr,wr,-wi,wi}
#define WS_SZ   (WARPS * KT * (G + 1) * 16)         // 20480
#define SMEM_BYTES (WS_OFF + WS_SZ)                 // 87552

__global__ __launch_bounds__(NTHREADS, 2)
void cv_attn_kernel(
    const float* __restrict__ qr, const float* __restrict__ qi,
    const float* __restrict__ kr, const float* __restrict__ ki,
    const float* __restrict__ vr, const float* __restrict__ vi,
    float* __restrict__ out, long long plane)
{
    extern __shared__ char smem[];
    float4 (*qs)[QPB + 1] = (float4 (*)[QPB + 1])(smem + QS_OFF);
    float2 (*ks)[KT + 1]  = (float2 (*)[KT + 1]) (smem + KS_OFF);
    float2 (*vs)[DHEAD]   = (float2 (*)[DHEAD])  (smem + VS_OFF);
    float4 (*ws)[KT][G+1] = (float4 (*)[KT][G+1])(smem + WS_OFF);

    const int tid  = threadIdx.x;
    const int w    = tid >> 5;
    const int lane = tid & 31;
    const int bh   = blockIdx.y;
    const int s0   = blockIdx.x * QPB;

    const long long bh_base = (long long)bh * S_LEN * DHEAD;
    const float inv_t = 0.125f;   // 1/TEMPERATURE, folded into Q

    // Load CTA's 32 queries, pre-packed for f32x2: {qr,qr,-qi,qi} * (1/t).
    for (int idx = tid; idx < QPB * DHEAD; idx += NTHREADS) {
        int qq = idx >> 6, d = idx & 63;          // consecutive tid -> d (coalesced)
        long long g = bh_base + (long long)(s0 + qq) * DHEAD + d;
        float xr = qr[g] * inv_t, xi = qi[g] * inv_t;
        qs[d][qq] = make_float4(xr, xr, -xi, xi);
    }

    float M[G], L[G];
    u64 acc0[G], acc1[G];       // {aR,aI} for d=lane and d=lane+32
    #pragma unroll
    for (int g = 0; g < G; g++) {
        M[g] = -1e30f; L[g] = 0.f;
        acc0[g] = pk2(0.f, 0.f); acc1[g] = pk2(0.f, 0.f);
    }

    for (int t0 = 0; t0 < S_LEN; t0 += KT) {
        __syncthreads();   // prev tile compute done (also orders q-store on iter 0)
        for (int idx = tid; idx < KT * DHEAD; idx += NTHREADS) {
            int ky = idx >> 6, d = idx & 63;
            long long g = bh_base + (long long)(t0 + ky) * DHEAD + d;
            ks[d][ky] = make_float2(kr[g], ki[g]);
            vs[ky][d] = make_float2(vr[g], vi[g]);
        }
        __syncthreads();

        // --- QK^T: lane = key, 4 queries from broadcast ---
        u64 sc[G];
        #pragma unroll
        for (int g = 0; g < G; g++) sc[g] = pk2(0.f, 0.f);

        #pragma unroll 16
        for (int d = 0; d < DHEAD; d++) {
            float2 kk = ks[d][lane];
            u64 kf = pk2(kk.x, kk.y);
            u64 kz = pk2(kk.y, kk.x);
            #pragma unroll
            for (int g = 0; g < G; g++) {
                float4 qv = qs[d][w * G + g];         // broadcast LDS.128
                sc[g] = fma2(pk2(qv.x, qv.y), kf, sc[g]);   // {re,im} += {qx,qx}*{kx,ky}
                sc[g] = fma2(pk2(qv.z, qv.w), kz, sc[g]);   //         += {-qy,qy}*{ky,kx}
            }
        }

        // --- online softmax over magnitudes (per query) ---
        #pragma unroll
        for (int g = 0; g < G; g++) {
            float re, im; upk2(sc[g], re, im);
            float mag2 = fmaxf(fmaf(re, re, im * im), 1e-24f);
            float mag  = mag2 * __frsqrt_rn(mag2);
            float m = mag;
            #pragma unroll
            for (int off = 16; off > 0; off >>= 1)
                m = fmaxf(m, __shfl_xor_sync(0xffffffffu, m, off));
            float newM = fmaxf(M[g], m);
            float corr = __expf(M[g] - newM);         // 0 on first tile
            float e    = __expf(mag - newM);
            float p    = __fdividef(e, fmaxf(mag, 1e-12f));
            float wr = re * p, wi = im * p;
            float ls = e;
            #pragma unroll
            for (int off = 16; off > 0; off >>= 1)
                ls += __shfl_xor_sync(0xffffffffu, ls, off);
            L[g] = fmaf(L[g], corr, ls);
            u64 c2 = pk2(corr, corr);
            acc0[g] = mul2(acc0[g], c2);
            acc1[g] = mul2(acc1[g], c2);
            ws[w][lane][g] = make_float4(wr, wr, -wi, wi);
            M[g] = newM;
        }
        __syncwarp();

        // --- A @ V: lane = output dim (d and d+32), weights from broadcast ---
        #pragma unroll 8
        for (int ky = 0; ky < KT; ky++) {
            float2 v0 = vs[ky][lane];
            float2 v1 = vs[ky][lane + 32];
            u64 v0f = pk2(v0.x, v0.y), v0s = pk2(v0.y, v0.x);
            u64 v1f = pk2(v1.x, v1.y), v1s = pk2(v1.y, v1.x);
            #pragma unroll
            for (int g = 0; g < G; g++) {
                float4 wv = ws[w][ky][g];             // broadcast LDS.128
                u64 wa = pk2(wv.x, wv.y);             // {wr,wr}
                u64 wb = pk2(wv.z, wv.w);             // {-wi,wi}
                acc0[g] = fma2(wa, v0f, acc0[g]);     // aR += wr*vx,  aI += wr*vy
                acc0[g] = fma2(wb, v0s, acc0[g]);     // aR += -wi*vy, aI += wi*vx
                acc1[g] = fma2(wa, v1f, acc1[g]);
                acc1[g] = fma2(wb, v1s, acc1[g]);
            }
        }
    }

    #pragma unroll
    for (int g = 0; g < G; g++) {
        float invL = __frcp_rn(L[g]);
        float a, b;
        long long ob = bh_base + (long long)(s0 + w * G + g) * DHEAD;
        upk2(acc0[g], a, b);
        out[ob + lane]              = a * invL;
        out[plane + ob + lane]      = b * invL;
        upk2(acc1[g], a, b);
        out[ob + lane + 32]         = a * invL;
        out[plane + ob + lane + 32] = b * invL;
    }
}

extern "C" void kernel_launch(void* const* d_in, const int* in_sizes, int n_in,
                              void* d_out, int out_size) {
    const float* qr = (const float*)d_in[0];
    const float* qi = (const float*)d_in[1];
    const float* kr = (const float*)d_in[2];
    const float* ki = (const float*)d_in[3];
    const float* vr = (const float*)d_in[4];
    const float* vi = (const float*)d_in[5];

    const long long plane = (long long)in_sizes[0];           // B*H*S*D
    const int bh = (int)(plane / ((long long)S_LEN * DHEAD)); // 32

    cudaFuncSetAttribute(cv_attn_kernel,
                         cudaFuncAttributeMaxDynamicSharedMemorySize, SMEM_BYTES);

    dim3 grid(S_LEN / QPB, bh);
    cv_attn_kernel<<<grid, NTHREADS, SMEM_BYTES>>>(qr, qi, kr, ki, vr, vi,
                                                   (float*)d_out, plane);
}

// round 4
// speedup vs baseline: 6.8468x; 4.6629x over previous
#include <cuda_runtime.h>
#include <cstdint>

// Complex attention via mma.sync tf32 (sm_103 baseline, no 'a' features).
// S = complex QK^T/t ; P = exp(|S|)*S/|S| ; O = P@V ; out = O / sum(exp|S|).

#define S_LEN   2048
#define DH      64
#define QT      128            // queries per CTA
#define NT      64             // keys per tile
#define NTILES  (S_LEN / NT)
#define THREADS 256
#define QSTR    68             // Q/K smem row stride (floats): conflict-free frags
#define VSTR    72             // V smem row stride

// smem float-offsets
#define QR_F     0
#define QI_F     (QT * QSTR)                    // 8704
#define QTOT_F   (2 * QT * QSTR)                // 17408
#define KR_F     0                              // within stage
#define KI_F     (NT * QSTR)                    // 4352
#define VR_F     (2 * NT * QSTR)                // 8704
#define VI_F     (2 * NT * QSTR + NT * VSTR)    // 13312
#define STG_F    (2 * NT * QSTR + 2 * NT * VSTR)// 17920 floats per stage
#define SMEM_BYTES ((QTOT_F + 2 * STG_F) * 4)   // 212992

__device__ __forceinline__ uint32_t cvta_s(const void* p) {
    uint32_t a;
    asm("{ .reg .u64 t; cvta.to.shared.u64 t, %1; cvt.u32.u64 %0, t; }" : "=r"(a) : "l"(p));
    return a;
}
__device__ __forceinline__ void cpa16(uint32_t dst, const void* src) {
    asm volatile("cp.async.ca.shared.global [%0], [%1], 16;" :: "r"(dst), "l"(src));
}
#define CP_COMMIT() asm volatile("cp.async.commit_group;" ::: "memory")
#define CP_WAIT0()  asm volatile("cp.async.wait_group 0;" ::: "memory")

__device__ __forceinline__ uint32_t f2tf(float x) {
    uint32_t r; asm("cvt.rna.tf32.f32 %0, %1;" : "=r"(r) : "f"(x)); return r;
}
__device__ __forceinline__ void mma8(float* d, const uint32_t* a, uint32_t b0, uint32_t b1) {
    asm volatile(
        "mma.sync.aligned.m16n8k8.row.col.f32.tf32.tf32.f32 "
        "{%0,%1,%2,%3}, {%4,%5,%6,%7}, {%8,%9}, {%0,%1,%2,%3};"
        : "+f"(d[0]), "+f"(d[1]), "+f"(d[2]), "+f"(d[3])
        : "r"(a[0]), "r"(a[1]), "r"(a[2]), "r"(a[3]), "r"(b0), "r"(b1));
}

// C-fragment (cols {2j,2j+1}) -> A-fragment (cols {j,j+4}) lane permutation.
__device__ __forceinline__ void xform(const float* c, uint32_t* a, int lane) {
    int j  = lane & 3;
    int s0 = (lane & ~3) | (j >> 1);
    int s1 = s0 + 2;
    float y00 = __shfl_sync(~0u, c[0], s0), y01 = __shfl_sync(~0u, c[1], s0);
    float y10 = __shfl_sync(~0u, c[0], s1), y11 = __shfl_sync(~0u, c[1], s1);
    float y20 = __shfl_sync(~0u, c[2], s0), y21 = __shfl_sync(~0u, c[3], s0);
    float y30 = __shfl_sync(~0u, c[2], s1), y31 = __shfl_sync(~0u, c[3], s1);
    bool od = (j & 1);
    a[0] = f2tf(od ? y01 : y00);
    a[1] = f2tf(od ? y21 : y20);
    a[2] = f2tf(od ? y11 : y10);
    a[3] = f2tf(od ? y31 : y30);
}

__global__ __launch_bounds__(THREADS, 1)
void cv_attn_mma_kernel(
    const float* __restrict__ qr, const float* __restrict__ qi,
    const float* __restrict__ kr, const float* __restrict__ ki,
    const float* __restrict__ vr, const float* __restrict__ vi,
    float* __restrict__ out, long long plane)
{
    extern __shared__ float sm[];
    const uint32_t smb = cvta_s(sm);

    const int tid  = threadIdx.x;
    const int w    = tid >> 5;
    const int lane = tid & 31;
    const int bh   = blockIdx.y;
    const int s0   = blockIdx.x * QT;
    const long long bb = (long long)bh * S_LEN * DH;

    auto load_stage = [&](int t, int s) {
        const uint32_t sbase = smb + (QTOT_F + s * STG_F) * 4;
        #pragma unroll
        for (int it = 0; it < 16; ++it) {
            int i = tid + it * THREADS;              // 4096 chunks total
            int half  = i >> 11;                     // 0:K 1:V
            int pl    = (i >> 10) & 1;               // 0:re 1:im
            int jj    = i & 1023;
            int r     = jj >> 4, c = jj & 15;
            const float* g;
            uint32_t foff;
            if (half == 0) {
                g = (pl ? ki : kr) + bb + (long long)(t * NT + r) * DH + c * 4;
                foff = (pl ? KI_F : KR_F) + r * QSTR + c * 4;
            } else {
                g = (pl ? vi : vr) + bb + (long long)(t * NT + r) * DH + c * 4;
                foff = (pl ? VI_F : VR_F) + r * VSTR + c * 4;
            }
            cpa16(sbase + foff * 4, g);
        }
    };

    // prologue: Q (both planes) + stage 0
    #pragma unroll
    for (int it = 0; it < 16; ++it) {
        int i = tid + it * THREADS;                  // 4096 chunks
        int pl = i >> 11;
        int jj = i & 2047;
        int r = jj >> 4, c = jj & 15;
        const float* g = (pl ? qi : qr) + bb + (long long)(s0 + r) * DH + c * 4;
        cpa16(smb + ((pl ? QI_F : QR_F) + r * QSTR + c * 4) * 4, g);
    }
    load_stage(0, 0);
    CP_COMMIT();

    float ore[8][4], oim[8][4];
    #pragma unroll
    for (int nb = 0; nb < 8; ++nb)
        #pragma unroll
        for (int c = 0; c < 4; ++c) { ore[nb][c] = 0.f; oim[nb][c] = 0.f; }
    float l0 = 0.f, l1 = 0.f;

    const int g4 = lane >> 2;       // group id (row / key / dim selector)
    const int j4 = lane & 3;
    const int r0 = w * 16 + g4;     // this thread's first Q row in CTA

    for (int t = 0; t < NTILES; ++t) {
        CP_WAIT0();
        __syncthreads();
        if (t + 1 < NTILES) { load_stage(t + 1, (t + 1) & 1); CP_COMMIT(); }

        const float* st = sm + QTOT_F + (t & 1) * STG_F;
        const float* Kr = st + KR_F;
        const float* Ki = st + KI_F;
        const float* Vr = st + VR_F;
        const float* Vi = st + VI_F;
        const float* Qr = sm + QR_F;
        const float* Qi = sm + QI_F;

        // ---- GEMM1: S[16 x 64] complex ----
        float sre[8][4], sim[8][4];
        #pragma unroll
        for (int nb = 0; nb < 8; ++nb)
            #pragma unroll
            for (int c = 0; c < 4; ++c) { sre[nb][c] = 0.f; sim[nb][c] = 0.f; }

        #pragma unroll
        for (int ks = 0; ks < 8; ++ks) {
            const int d0 = ks * 8 + j4;
            uint32_t aqr[4], aqi[4], anqi[4];
            aqr[0] = f2tf(Qr[ r0      * QSTR + d0    ]);
            aqr[1] = f2tf(Qr[(r0 + 8) * QSTR + d0    ]);
            aqr[2] = f2tf(Qr[ r0      * QSTR + d0 + 4]);
            aqr[3] = f2tf(Qr[(r0 + 8) * QSTR + d0 + 4]);
            aqi[0] = f2tf(Qi[ r0      * QSTR + d0    ]);
            aqi[1] = f2tf(Qi[(r0 + 8) * QSTR + d0    ]);
            aqi[2] = f2tf(Qi[ r0      * QSTR + d0 + 4]);
            aqi[3] = f2tf(Qi[(r0 + 8) * QSTR + d0 + 4]);
            #pragma unroll
            for (int k = 0; k < 4; ++k) anqi[k] = aqi[k] ^ 0x80000000u;

            #pragma unroll
            for (int nb = 0; nb < 8; ++nb) {
                const int ka = (nb * 8 + g4) * QSTR + ks * 8 + j4;
                uint32_t br0 = f2tf(Kr[ka]), br1 = f2tf(Kr[ka + 4]);
                uint32_t bi0 = f2tf(Ki[ka]), bi1 = f2tf(Ki[ka + 4]);
                mma8(sre[nb], aqr,  br0, br1);
                mma8(sre[nb], anqi, bi0, bi1);
                mma8(sim[nb], aqr,  bi0, bi1);
                mma8(sim[nb], aqi,  br0, br1);
            }
        }

        // ---- softmax epilogue: S -> P, accumulate L ----
        #pragma unroll
        for (int nb = 0; nb < 8; ++nb) {
            #pragma unroll
            for (int c = 0; c < 4; ++c) {
                float re = sre[nb][c], im = sim[nb][c];
                float m2  = fmaxf(fmaf(re, re, im * im), 1e-24f);
                float inv = rsqrtf(m2);
                float mag = m2 * inv;
                float e   = __expf(0.125f * mag);    // temperature fold
                if (c < 2) l0 += e; else l1 += e;
                float p = e * inv;
                sre[nb][c] = re * p;
                sim[nb][c] = im * p;
            }
        }

        // ---- GEMM2: O += P @ V (complex) ----
        #pragma unroll
        for (int ks = 0; ks < 8; ++ks) {
            uint32_t apr[4], api[4], anpi[4];
            xform(sre[ks], apr, lane);
            xform(sim[ks], api, lane);
            #pragma unroll
            for (int k = 0; k < 4; ++k) anpi[k] = api[k] ^ 0x80000000u;

            #pragma unroll
            for (int nb = 0; nb < 8; ++nb) {
                const int va = (ks * 8 + j4) * VSTR + nb * 8 + g4;
                uint32_t vr0 = f2tf(Vr[va]), vr1 = f2tf(Vr[va + 4 * VSTR]);
                uint32_t vi0 = f2tf(Vi[va]), vi1 = f2tf(Vi[va + 4 * VSTR]);
                mma8(ore[nb], apr,  vr0, vr1);
                mma8(ore[nb], anpi, vi0, vi1);
                mma8(oim[nb], apr,  vi0, vi1);
                mma8(oim[nb], api,  vr0, vr1);
            }
        }
    }

    __syncthreads();   // everyone done with Q region; reuse as output stage

    l0 += __shfl_xor_sync(~0u, l0, 1); l0 += __shfl_xor_sync(~0u, l0, 2);
    l1 += __shfl_xor_sync(~0u, l1, 1); l1 += __shfl_xor_sync(~0u, l1, 2);
    float il0 = 1.0f / l0, il1 = 1.0f / l1;

    float* stR = sm + QR_F;
    float* stI = sm + QI_F;
    #pragma unroll
    for (int nb = 0; nb < 8; ++nb) {
        int d0 = nb * 8 + 2 * j4;
        stR[ r0      * QSTR + d0    ] = ore[nb][0] * il0;
        stR[ r0      * QSTR + d0 + 1] = ore[nb][1] * il0;
        stR[(r0 + 8) * QSTR + d0    ] = ore[nb][2] * il1;
        stR[(r0 + 8) * QSTR + d0 + 1] = ore[nb][3] * il1;
        stI[ r0      * QSTR + d0    ] = oim[nb][0] * il0;
        stI[ r0      * QSTR + d0 + 1] = oim[nb][1] * il0;
        stI[(r0 + 8) * QSTR + d0    ] = oim[nb][2] * il1;
        stI[(r0 + 8) * QSTR + d0 + 1] = oim[nb][3] * il1;
    }
    __syncthreads();

    for (int i = tid; i < QT * 16; i += THREADS) {
        int r = i >> 4, c = i & 15;
        long long ob = bb + (long long)(s0 + r) * DH + c * 4;
        *(float4*)(out + ob)         = *(float4*)(stR + r * QSTR + c * 4);
        *(float4*)(out + plane + ob) = *(float4*)(stI + r * QSTR + c * 4);
    }
}

extern "C" void kernel_launch(void* const* d_in, const int* in_sizes, int n_in,
                              void* d_out, int out_size) {
    const float* qr = (const float*)d_in[0];
    const float* qi = (const float*)d_in[1];
    const float* kr = (const float*)d_in[2];
    const float* ki = (const float*)d_in[3];
    const float* vr = (const float*)d_in[4];
    const float* vi = (const float*)d_in[5];

    const long long plane = (long long)in_sizes[0];            // B*H*S*D
    const int bh = (int)(plane / ((long long)S_LEN * DH));     // 32

    static int configured = 0;
    if (!configured) {
        cudaFuncSetAttribute(cv_attn_mma_kernel,
                             cudaFuncAttributeMaxDynamicSharedMemorySize, SMEM_BYTES);
        configured = 1;
    }

    dim3 grid(S_LEN / QT, bh);    // 16 x 32 = 512 CTAs
    cv_attn_mma_kernel<<<grid, THREADS, SMEM_BYTES>>>(qr, qi, kr, ki, vr, vi,
                                                      (float*)d_out, plane);
}